// round 1
// baseline (speedup 1.0000x reference)
#include <cuda_runtime.h>

// VectorQuantizer: B=32, D=64, T=8192, K=512
// in[0]: x   [B, D, T] float32
// in[1]: emb [K, D]    float32
// out:  [2, B, D, T] float32  (quantized_st, quantized) concatenated
//
// Per token (b, t): latent = argmin_k fl(fl(x2 - 2*dot(x, e_k)) + e2_k)
// (first-index wins ties, matching jnp.argmin), then
//   quantized_st = fl(x + fl(q - x)),  quantized = q  where q = emb[latent].

#define BB 32
#define DD 64
#define TT 8192
#define KK 512
#define TPB 256
#define TOK_PER_CTA 512        // 2 tokens per thread
#define NCHUNK ((BB * TT) / TOK_PER_CTA)   // 512 CTAs
#define SMEM_FLOATS (KK * DD + KK)
#define SMEM_BYTES (SMEM_FLOATS * 4)

extern __shared__ float s_dyn[];

__global__ void __launch_bounds__(TPB, 1)
vq_kernel(const float* __restrict__ x,
          const float* __restrict__ emb,
          float* __restrict__ out) {
    float* s_emb = s_dyn;           // [KK][DD]
    float* s_e2  = s_dyn + KK * DD; // [KK]
    const int tid = threadIdx.x;

    // ---- Load codebook into shared memory (32768 floats = 8192 float4) ----
    {
        const float4* e4 = reinterpret_cast<const float4*>(emb);
        float4* s4 = reinterpret_cast<float4*>(s_emb);
        #pragma unroll
        for (int i = 0; i < (KK * DD / 4) / TPB; i++)
            s4[tid + i * TPB] = e4[tid + i * TPB];
    }
    __syncthreads();

    // ---- e2[k] = sum_d emb[k][d]^2 (mul then add, rounded ops) ----
    for (int r = tid; r < KK; r += TPB) {
        const float* row = s_emb + r * DD;
        float s = 0.0f;
        #pragma unroll
        for (int d = 0; d < DD; d++)
            s = __fadd_rn(s, __fmul_rn(row[d], row[d]));
        s_e2[r] = s;
    }
    __syncthreads();

    // ---- token mapping: CTA covers 512 consecutive t within one b ----
    const int chunk = blockIdx.x;
    const long long g0 = (long long)chunk * TOK_PER_CTA;
    const int b  = (int)(g0 / TT);
    const int t0 = (int)(g0 % TT);
    const float* xbase = x + (long long)b * DD * TT;
    const int ta = t0 + tid;          // token A
    const int tc = t0 + tid + TPB;    // token B

    // ---- load x for both tokens into registers (coalesced per d-row) ----
    float xa[DD], xc[DD];
    #pragma unroll
    for (int d = 0; d < DD; d++) {
        xa[d] = xbase[(long long)d * TT + ta];
        xc[d] = xbase[(long long)d * TT + tc];
    }

    // ---- x2 (mul + add, no FMA contraction) ----
    float x2a = 0.0f, x2c = 0.0f;
    #pragma unroll
    for (int d = 0; d < DD; d++) {
        x2a = __fadd_rn(x2a, __fmul_rn(xa[d], xa[d]));
        x2c = __fadd_rn(x2c, __fmul_rn(xc[d], xc[d]));
    }

    // ---- argmin over K, 4 codes at a time ----
    float bda = 3.402823466e38f, bdc = 3.402823466e38f;
    int   bia = 0, bic = 0;

    for (int k = 0; k < KK; k += 4) {
        float a0 = 0.f, a1 = 0.f, a2 = 0.f, a3 = 0.f;
        float c0 = 0.f, c1 = 0.f, c2 = 0.f, c3 = 0.f;
        const float4* r0 = reinterpret_cast<const float4*>(s_emb + (k + 0) * DD);
        const float4* r1 = reinterpret_cast<const float4*>(s_emb + (k + 1) * DD);
        const float4* r2 = reinterpret_cast<const float4*>(s_emb + (k + 2) * DD);
        const float4* r3 = reinterpret_cast<const float4*>(s_emb + (k + 3) * DD);
        #pragma unroll
        for (int q = 0; q < DD / 4; q++) {
            const float4 e0 = r0[q];
            const float4 e1 = r1[q];
            const float4 e2v = r2[q];
            const float4 e3 = r3[q];
            const float pa0 = xa[q * 4 + 0], pa1 = xa[q * 4 + 1];
            const float pa2 = xa[q * 4 + 2], pa3 = xa[q * 4 + 3];
            const float pc0 = xc[q * 4 + 0], pc1 = xc[q * 4 + 1];
            const float pc2 = xc[q * 4 + 2], pc3 = xc[q * 4 + 3];

            a0 = fmaf(pa0, e0.x, a0); a0 = fmaf(pa1, e0.y, a0);
            a0 = fmaf(pa2, e0.z, a0); a0 = fmaf(pa3, e0.w, a0);
            a1 = fmaf(pa0, e1.x, a1); a1 = fmaf(pa1, e1.y, a1);
            a1 = fmaf(pa2, e1.z, a1); a1 = fmaf(pa3, e1.w, a1);
            a2 = fmaf(pa0, e2v.x, a2); a2 = fmaf(pa1, e2v.y, a2);
            a2 = fmaf(pa2, e2v.z, a2); a2 = fmaf(pa3, e2v.w, a2);
            a3 = fmaf(pa0, e3.x, a3); a3 = fmaf(pa1, e3.y, a3);
            a3 = fmaf(pa2, e3.z, a3); a3 = fmaf(pa3, e3.w, a3);

            c0 = fmaf(pc0, e0.x, c0); c0 = fmaf(pc1, e0.y, c0);
            c0 = fmaf(pc2, e0.z, c0); c0 = fmaf(pc3, e0.w, c0);
            c1 = fmaf(pc0, e1.x, c1); c1 = fmaf(pc1, e1.y, c1);
            c1 = fmaf(pc2, e1.z, c1); c1 = fmaf(pc3, e1.w, c1);
            c2 = fmaf(pc0, e2v.x, c2); c2 = fmaf(pc1, e2v.y, c2);
            c2 = fmaf(pc2, e2v.z, c2); c2 = fmaf(pc3, e2v.w, c2);
            c3 = fmaf(pc0, e3.x, c3); c3 = fmaf(pc1, e3.y, c3);
            c3 = fmaf(pc2, e3.z, c3); c3 = fmaf(pc3, e3.w, c3);
        }
        // dist = fl(fl(x2 - 2*xe) + e2); 2*xe is exact. Ascending k, strict <.
        const float ee0 = s_e2[k + 0], ee1 = s_e2[k + 1];
        const float ee2 = s_e2[k + 2], ee3 = s_e2[k + 3];

        float d0 = __fadd_rn(__fsub_rn(x2a, 2.0f * a0), ee0);
        if (d0 < bda) { bda = d0; bia = k + 0; }
        float d1 = __fadd_rn(__fsub_rn(x2a, 2.0f * a1), ee1);
        if (d1 < bda) { bda = d1; bia = k + 1; }
        float d2 = __fadd_rn(__fsub_rn(x2a, 2.0f * a2), ee2);
        if (d2 < bda) { bda = d2; bia = k + 2; }
        float d3 = __fadd_rn(__fsub_rn(x2a, 2.0f * a3), ee3);
        if (d3 < bda) { bda = d3; bia = k + 3; }

        float g0v = __fadd_rn(__fsub_rn(x2c, 2.0f * c0), ee0);
        if (g0v < bdc) { bdc = g0v; bic = k + 0; }
        float g1v = __fadd_rn(__fsub_rn(x2c, 2.0f * c1), ee1);
        if (g1v < bdc) { bdc = g1v; bic = k + 1; }
        float g2v = __fadd_rn(__fsub_rn(x2c, 2.0f * c2), ee2);
        if (g2v < bdc) { bdc = g2v; bic = k + 2; }
        float g3v = __fadd_rn(__fsub_rn(x2c, 2.0f * c3), ee3);
        if (g3v < bdc) { bdc = g3v; bic = k + 3; }
    }

    // ---- write outputs: [0] = straight-through, [1] = quantized ----
    float* o_st = out;
    float* o_q  = out + (long long)BB * DD * TT;
    const float* qa = s_emb + bia * DD;
    const float* qc = s_emb + bic * DD;
    const long long obase = (long long)b * DD * TT;

    #pragma unroll
    for (int d = 0; d < DD; d++) {
        const long long oa = obase + (long long)d * TT + ta;
        const long long oc = obase + (long long)d * TT + tc;
        const float q1 = qa[d];
        const float q2 = qc[d];
        // quantized_st = fl(x + fl(q - x))  (matches jnp straight-through)
        o_st[oa] = __fadd_rn(xa[d], __fsub_rn(q1, xa[d]));
        o_q[oa]  = q1;
        o_st[oc] = __fadd_rn(xc[d], __fsub_rn(q2, xc[d]));
        o_q[oc]  = q2;
    }
}

extern "C" void kernel_launch(void* const* d_in, const int* in_sizes, int n_in,
                              void* d_out, int out_size) {
    const float* x   = (const float*)d_in[0];
    const float* emb = (const float*)d_in[1];
    float* out = (float*)d_out;
    (void)in_sizes; (void)n_in; (void)out_size;

    cudaFuncSetAttribute(vq_kernel,
                         cudaFuncAttributeMaxDynamicSharedMemorySize,
                         SMEM_BYTES);
    vq_kernel<<<NCHUNK, TPB, SMEM_BYTES>>>(x, emb, out);
}